// round 8
// baseline (speedup 1.0000x reference)
#include <cuda_runtime.h>
#include <math.h>
#include <float.h>

#define QLEN 1024
#define DMODEL 4096
#define NH 32
#define NKV 8
#define HD 128
#define OUTL 16
#define KEEP 256

// ---------------- scratch (static device globals; no allocation) ----------------
__device__ float g_qlin[QLEN * DMODEL];
__device__ float g_klin[QLEN * NKV * HD];
__device__ float g_vlin[QLEN * NKV * HD];
__device__ float g_qr[NH * QLEN * HD];
__device__ float g_kr[NKV * QLEN * HD];
__device__ float g_vr[NKV * QLEN * HD];
__device__ float g_gq[NH * QLEN * OUTL];
__device__ float g_gk[NH * QLEN * OUTL];
__device__ float g_o[QLEN * NH * HD];

// ---------------- 3xTF32 tensor-core GEMM, split-at-load + reg double buffer ----
// Numerically identical to round 7 (same splits, same MMA order, same folds).
#define GBM 128
#define GBN 64
#define GBK 32
#define KP (GBK + 4)

__device__ __forceinline__ void tf32_split(float x, unsigned& hi, unsigned& lo) {
    unsigned h;
    asm("cvt.rna.tf32.f32 %0, %1;" : "=r"(h) : "f"(x));
    float r = __fadd_rn(x, -__uint_as_float(h));
    unsigned l;
    asm("cvt.rna.tf32.f32 %0, %1;" : "=r"(l) : "f"(r));
    hi = h; lo = l;
}

__device__ __forceinline__ void mma_tf32(float* d, const unsigned* a, const unsigned* b) {
    asm volatile(
        "mma.sync.aligned.m16n8k8.row.col.f32.tf32.tf32.f32 "
        "{%0,%1,%2,%3}, {%4,%5,%6,%7}, {%8,%9}, {%0,%1,%2,%3};"
        : "+f"(d[0]), "+f"(d[1]), "+f"(d[2]), "+f"(d[3])
        : "r"(a[0]), "r"(a[1]), "r"(a[2]), "r"(a[3]), "r"(b[0]), "r"(b[1]));
}

__global__ __launch_bounds__(256) void gemm_tf32(
    const float* __restrict__ A,
    const float* __restrict__ B0, float* __restrict__ C0,
    const float* __restrict__ B1, float* __restrict__ C1,
    int N, int K)
{
    const float* B = (blockIdx.z == 0) ? B0 : B1;
    float* C = (blockIdx.z == 0) ? C0 : C1;

    __shared__ unsigned Ah[GBM][KP], Al[GBM][KP];   // 18KB + 18KB
    __shared__ unsigned Bh[GBN][KP], Bl[GBN][KP];   // 9KB + 9KB

    int tid = threadIdx.x;
    int lane = tid & 31;
    int wid = tid >> 5;
    int wm = (wid >> 1) * 32;
    int wn = (wid & 1) * 32;
    int g = lane >> 2;
    int t4 = lane & 3;

    int bm = blockIdx.y * GBM;
    int bn = blockIdx.x * GBN;

    // per-thread load coords
    int arow[4], acol[4];
#pragma unroll
    for (int i = 0; i < 4; ++i) {
        int idx = tid + i * 256;
        arow[i] = idx >> 3;
        acol[i] = (idx & 7) << 2;
    }
    int bkrow[2], bncol[2];
#pragma unroll
    for (int i = 0; i < 2; ++i) {
        int idx = tid + i * 256;
        bkrow[i] = idx >> 4;
        bncol[i] = (idx & 15) << 2;
    }

    float acc[2][4][4], mst[2][4][4];
#pragma unroll
    for (int mt = 0; mt < 2; ++mt)
#pragma unroll
        for (int nt = 0; nt < 4; ++nt)
#pragma unroll
            for (int r = 0; r < 4; ++r) { acc[mt][nt][r] = 0.f; mst[mt][nt][r] = 0.f; }

    float4 ra[4], rb[2];
    // prefetch tile 0
#pragma unroll
    for (int i = 0; i < 4; ++i)
        ra[i] = *(const float4*)&A[(size_t)(bm + arow[i]) * K + acol[i]];
#pragma unroll
    for (int i = 0; i < 2; ++i)
        rb[i] = *(const float4*)&B[(size_t)bkrow[i] * N + bn + bncol[i]];

    int ntiles = K / GBK;
    for (int t = 0; t < ntiles; ++t) {
        // split + store current regs to smem
#pragma unroll
        for (int i = 0; i < 4; ++i) {
            unsigned h0,l0,h1,l1,h2,l2,h3,l3;
            tf32_split(ra[i].x, h0, l0);
            tf32_split(ra[i].y, h1, l1);
            tf32_split(ra[i].z, h2, l2);
            tf32_split(ra[i].w, h3, l3);
            int r = arow[i], c = acol[i];
            Ah[r][c] = h0; Ah[r][c+1] = h1; Ah[r][c+2] = h2; Ah[r][c+3] = h3;
            Al[r][c] = l0; Al[r][c+1] = l1; Al[r][c+2] = l2; Al[r][c+3] = l3;
        }
#pragma unroll
        for (int i = 0; i < 2; ++i) {
            unsigned h0,l0,h1,l1,h2,l2,h3,l3;
            tf32_split(rb[i].x, h0, l0);
            tf32_split(rb[i].y, h1, l1);
            tf32_split(rb[i].z, h2, l2);
            tf32_split(rb[i].w, h3, l3);
            int k = bkrow[i], n4 = bncol[i];
            Bh[n4][k] = h0; Bh[n4+1][k] = h1; Bh[n4+2][k] = h2; Bh[n4+3][k] = h3;
            Bl[n4][k] = l0; Bl[n4+1][k] = l1; Bl[n4+2][k] = l2; Bl[n4+3][k] = l3;
        }
        __syncthreads();

        // prefetch next tile (global -> regs), overlapped with MMA below
        if (t + 1 < ntiles) {
            int k0 = (t + 1) * GBK;
#pragma unroll
            for (int i = 0; i < 4; ++i)
                ra[i] = *(const float4*)&A[(size_t)(bm + arow[i]) * K + k0 + acol[i]];
#pragma unroll
            for (int i = 0; i < 2; ++i)
                rb[i] = *(const float4*)&B[(size_t)(k0 + bkrow[i]) * N + bn + bncol[i]];
        }

#pragma unroll
        for (int ks = 0; ks < GBK / 8; ++ks) {
            int kb = ks * 8;
            unsigned ah[2][4], al[2][4];
#pragma unroll
            for (int mt = 0; mt < 2; ++mt) {
                int r0 = wm + mt * 16;
                ah[mt][0] = Ah[r0 + g][kb + t4];
                ah[mt][1] = Ah[r0 + g + 8][kb + t4];
                ah[mt][2] = Ah[r0 + g][kb + t4 + 4];
                ah[mt][3] = Ah[r0 + g + 8][kb + t4 + 4];
                al[mt][0] = Al[r0 + g][kb + t4];
                al[mt][1] = Al[r0 + g + 8][kb + t4];
                al[mt][2] = Al[r0 + g][kb + t4 + 4];
                al[mt][3] = Al[r0 + g + 8][kb + t4 + 4];
            }
            unsigned bh[4][2], bl[4][2];
#pragma unroll
            for (int nt = 0; nt < 4; ++nt) {
                int col = wn + nt * 8 + g;
                bh[nt][0] = Bh[col][kb + t4];
                bh[nt][1] = Bh[col][kb + t4 + 4];
                bl[nt][0] = Bl[col][kb + t4];
                bl[nt][1] = Bl[col][kb + t4 + 4];
            }
#pragma unroll
            for (int mt = 0; mt < 2; ++mt)
#pragma unroll
                for (int nt = 0; nt < 4; ++nt) {
                    mma_tf32(acc[mt][nt], ah[mt], bh[nt]);
                    mma_tf32(acc[mt][nt], al[mt], bh[nt]);
                    mma_tf32(acc[mt][nt], ah[mt], bl[nt]);
                }
        }
        __syncthreads();

        if ((t & 3) == 3) {
#pragma unroll
            for (int mt = 0; mt < 2; ++mt)
#pragma unroll
                for (int nt = 0; nt < 4; ++nt)
#pragma unroll
                    for (int r = 0; r < 4; ++r) {
                        mst[mt][nt][r] = __fadd_rn(mst[mt][nt][r], acc[mt][nt][r]);
                        acc[mt][nt][r] = 0.f;
                    }
        }
    }

#pragma unroll
    for (int mt = 0; mt < 2; ++mt)
#pragma unroll
        for (int nt = 0; nt < 4; ++nt) {
            int r0 = bm + wm + mt * 16 + g;
            int c0 = bn + wn + nt * 8 + t4 * 2;
            *(float2*)&C[(size_t)r0 * N + c0] =
                make_float2(mst[mt][nt][0], mst[mt][nt][1]);
            *(float2*)&C[(size_t)(r0 + 8) * N + c0] =
                make_float2(mst[mt][nt][2], mst[mt][nt][3]);
        }
}

// ---------------- RoPE + layout transpose (precision-matched) ----------------
__global__ void rope_kernel()
{
    int p = blockIdx.x;
    int hh = blockIdx.y;
    int d = threadIdx.x;

    int i = d & 63;
    float P = (float)pow(10000.0, (double)(2 * i) / 128.0);
    float invf = __fdiv_rn(1.0f, P);
    float ang = __fmul_rn((float)p, invf);
    float c = (float)cos((double)ang);
    float s = (float)sin((double)ang);

    if (hh < NH) {
        const float* base = &g_qlin[(size_t)p * DMODEL + hh * HD];
        float v = base[d];
        float other = (d < 64) ? -base[d + 64] : base[d - 64];
        g_qr[((size_t)hh * QLEN + p) * HD + d] =
            __fadd_rn(__fmul_rn(v, c), __fmul_rn(other, s));
    } else if (hh < NH + NKV) {
        int kvh = hh - NH;
        const float* base = &g_klin[(size_t)p * (NKV * HD) + kvh * HD];
        float v = base[d];
        float other = (d < 64) ? -base[d + 64] : base[d - 64];
        g_kr[((size_t)kvh * QLEN + p) * HD + d] =
            __fadd_rn(__fmul_rn(v, c), __fmul_rn(other, s));
    } else {
        int kvh = hh - NH - NKV;
        g_vr[((size_t)kvh * QLEN + p) * HD + d] =
            g_vlin[(size_t)p * (NKV * HD) + kvh * HD + d];
    }
}

// ---------------- label build: 8 warps per block, one (p,h) per warp ------------
__global__ __launch_bounds__(256) void gqk_kernel(const int* __restrict__ sorted_channel)
{
    int warp = threadIdx.x >> 5;
    int lane = threadIdx.x & 31;
    int p = blockIdx.x;
    int h = blockIdx.y * 8 + warp;

    int j = lane & 15;
    bool isK = lane >= 16;

    int ch = sorted_channel[h * HD + j];
    float t;
    if (!isK) t = g_qr[((size_t)h * QLEN + p) * HD + ch];
    else      t = g_kr[((size_t)(h >> 2) * QLEN + p) * HD + ch];

    float mn = t, mx = t;
#pragma unroll
    for (int off = 1; off < 16; off <<= 1) {
        mn = fminf(mn, __shfl_xor_sync(0xffffffffu, mn, off));
        mx = fmaxf(mx, __shfl_xor_sync(0xffffffffu, mx, off));
    }
    float rng = __fadd_rn(mx, -mn);
    if (rng == 0.0f) rng = 1.0f;
    float scale = __fdiv_rn(15.0f, rng);
    float qv = rintf(__fmul_rn(__fadd_rn(t, -mn), scale));
    qv = fminf(fmaxf(qv, 0.0f), 15.0f);
    float outv = __fadd_rn(__fdiv_rn(qv, scale), mn);

    if (!isK) g_gq[((size_t)h * QLEN + p) * OUTL + j] = outv;
    else      g_gk[((size_t)h * QLEN + p) * OUTL + j] = outv;
}

// ---------------- fused gattn -> stable top-256 -> attn -> softmax -> AV ----
__global__ __launch_bounds__(256) void attn_kernel()
{
    int p = blockIdx.x;
    int h = blockIdx.y;
    int kvh = h >> 2;
    int tid = threadIdx.x;
    int lane = tid & 31;
    int warp = tid >> 5;

    __shared__ float gq_s[OUTL];
    __shared__ float q_s[HD];
    __shared__ unsigned keys[QLEN];
    __shared__ unsigned hist[256];
    __shared__ unsigned wsum[8];
    __shared__ int kept_raw[KEEP];
    __shared__ int kept_idx[KEEP];
    __shared__ float attw[KEEP];
    __shared__ float obuf[HD];
    __shared__ int kcount;
    __shared__ unsigned sh_prefix;
    __shared__ int sh_want;
    __shared__ int wcnt[8];
    __shared__ int eqbase;
    __shared__ float red[8];
    __shared__ float sh_scalar;

    if (tid < OUTL) gq_s[tid] = g_gq[((size_t)h * QLEN + p) * OUTL + tid];
    if (tid < HD)   q_s[tid] = g_qr[((size_t)h * QLEN + p) * HD + tid];
    if (tid == 0) { kcount = 0; eqbase = 0; }
    __syncthreads();

    int nvalid = p + 1;

    // 1. gattn keys: strict ascending sequential FMA chain, exact /4.
    for (int j = tid; j < nvalid; j += 256) {
        const float* g = &g_gk[((size_t)h * QLEN + j) * OUTL];
        float s = __fmul_rn(g[0], gq_s[0]);
#pragma unroll
        for (int d = 1; d < OUTL; ++d)
            s = __fmaf_rn(g[d], gq_s[d], s);
        s = __fmul_rn(s, 0.25f);
        unsigned u = __float_as_uint(s);
        if ((u << 1) == 0u) u = 0u;          // -0.0 == +0.0
        u ^= (u & 0x80000000u) ? 0xFFFFFFFFu : 0x80000000u;
        keys[j] = u;
    }
    __syncthreads();

    // 2. stable top-KEEP selection (radix; warp-shfl suffix scan)
    int cnt;
    if (nvalid <= KEEP) {
        for (int j = tid; j < nvalid; j += 256) kept_idx[j] = j;
        cnt = nvalid;
        __syncthreads();
    } else {
        unsigned prefix = 0;
        int want = KEEP;
        for (int byte = 3; byte >= 0; --byte) {
            hist[tid] = 0;
            __syncthreads();
            int shift = byte * 8;
            unsigned pmask = (byte == 3) ? 0u : (0xFFFFFFFFu << (shift + 8));
            for (int j = tid; j < nvalid; j += 256) {
                unsigned u = keys[j];
                if ((u & pmask) == prefix)
                    atomicAdd(&hist[(u >> shift) & 255u], 1u);
            }
            __syncthreads();

            unsigned hv = hist[tid];
            unsigned s = hv;
#pragma unroll
            for (int off = 1; off < 32; off <<= 1) {
                unsigned t2 = __shfl_down_sync(0xffffffffu, s, off);
                if (lane + off < 32) s += t2;
            }
            if (lane == 0) wsum[warp] = s;   // warp-chunk total = suffix at its base
            __syncthreads();
            unsigned add = 0;
#pragma unroll
            for (int w = 0; w < 8; ++w)
                if (w > warp) add += wsum[w];
            unsigned suft = s + add;         // suffix sum over bins >= tid
            unsigned above = suft - hv;
            if (suft >= (unsigned)want && above < (unsigned)want) {
                sh_prefix = prefix | ((unsigned)tid << shift);
                sh_want = want - (int)above;
            }
            __syncthreads();
            prefix = sh_prefix;
            want = sh_want;
            __syncthreads();
        }
        unsigned uT = prefix;
        int r = want;

        for (int chunk = 0; chunk < QLEN / 256; ++chunk) {
            int j = chunk * 256 + tid;
            bool isval = j < nvalid;
            unsigned u = isval ? keys[j] : 0u;
            bool gt = isval && (u > uT);
            bool eq = isval && (u == uT);
            if (gt) { int s = atomicAdd(&kcount, 1); kept_raw[s] = j; }
            unsigned bal = __ballot_sync(0xffffffffu, eq);
            if (lane == 0) wcnt[warp] = __popc(bal);
            __syncthreads();
            int woff = 0;
            for (int w = 0; w < warp; ++w) woff += wcnt[w];
            int eqidx = eqbase + woff + __popc(bal & ((1u << lane) - 1u));
            if (eq && eqidx < r) { int s = atomicAdd(&kcount, 1); kept_raw[s] = j; }
            __syncthreads();
            if (tid == 0) {
                int tot = 0;
                for (int w = 0; w < 8; ++w) tot += wcnt[w];
                eqbase += tot;
            }
            __syncthreads();
        }
        cnt = kcount;
        __syncthreads();

        // sort kept indices ascending
        if (tid < cnt) {
            int mine = kept_raw[tid];
            int rk = 0;
            for (int s = 0; s < cnt; ++s) rk += (kept_raw[s] < mine);
            kept_idx[rk] = mine;
        }
        __syncthreads();
    }
    __syncthreads();

    // 3. attn scores on kept columns (warp per column, float4 loads)
    {
        float4 qreg = *(const float4*)&q_s[lane * 4];
        for (int c = warp; c < cnt; c += 8) {
            int j = kept_idx[c];
            float4 kv = *(const float4*)&g_kr[((size_t)kvh * QLEN + j) * HD + lane * 4];
            float s = __fmul_rn(qreg.x, kv.x);
            s = __fmaf_rn(qreg.y, kv.y, s);
            s = __fmaf_rn(qreg.z, kv.z, s);
            s = __fmaf_rn(qreg.w, kv.w, s);
#pragma unroll
            for (int off = 16; off; off >>= 1) s += __shfl_xor_sync(0xffffffffu, s, off);
            if (lane == 0) attw[c] = s / 11.313708498984761f;
        }
    }
    __syncthreads();

    // 4. softmax over kept (exp via double -> correctly rounded fp32)
    float vmax = -FLT_MAX;
    for (int c = tid; c < cnt; c += 256) vmax = fmaxf(vmax, attw[c]);
#pragma unroll
    for (int off = 16; off; off >>= 1)
        vmax = fmaxf(vmax, __shfl_xor_sync(0xffffffffu, vmax, off));
    if (lane == 0) red[warp] = vmax;
    __syncthreads();
    if (warp == 0) {
        float m = (lane < 8) ? red[lane] : -FLT_MAX;
#pragma unroll
        for (int off = 4; off; off >>= 1)
            m = fmaxf(m, __shfl_xor_sync(0xffffffffu, m, off));
        if (lane == 0) sh_scalar = m;
    }
    __syncthreads();
    float M = sh_scalar;

    float lsum = 0.f;
    for (int c = tid; c < cnt; c += 256) {
        float e = (float)exp((double)__fadd_rn(attw[c], -M));
        attw[c] = e;
        lsum += e;
    }
#pragma unroll
    for (int off = 16; off; off >>= 1)
        lsum += __shfl_xor_sync(0xffffffffu, lsum, off);
    if (lane == 0) red[warp] = lsum;
    __syncthreads();
    if (warp == 0) {
        float s2 = (lane < 8) ? red[lane] : 0.f;
#pragma unroll
        for (int off = 4; off; off >>= 1)
            s2 += __shfl_xor_sync(0xffffffffu, s2, off);
        if (lane == 0) sh_scalar = s2;
    }
    __syncthreads();
    float denom = sh_scalar;

    for (int c = tid; c < cnt; c += 256)
        attw[c] = __fdiv_rn(attw[c], denom);
    __syncthreads();

    // 5. AV: two halves of the block split the kept columns
    {
        int d = tid & 127;
        int half = tid >> 7;
        float acc = 0.f;
        const float* vbase = &g_vr[(size_t)kvh * QLEN * HD + d];
        for (int c = half; c < cnt; c += 2)
            acc = __fmaf_rn(attw[c], __ldg(&vbase[(size_t)kept_idx[c] * HD]), acc);
        if (half == 0) obuf[d] = acc;
        __syncthreads();
        if (half == 1)
            g_o[(size_t)p * (NH * HD) + h * HD + d] = __fadd_rn(obuf[d], acc);
    }
}

// ---------------- launch ----------------
extern "C" void kernel_launch(void* const* d_in, const int* in_sizes, int n_in,
                              void* d_out, int out_size)
{
    const float* hidden = (const float*)d_in[0];
    const float* Wq = (const float*)d_in[3];
    const float* Wk = (const float*)d_in[4];
    const float* Wv = (const float*)d_in[5];
    const float* Wo = (const float*)d_in[6];
    const int* sorted_channel = (const int*)d_in[7];
    float* out = (float*)d_out;

    float *qlin, *klin, *vlin, *o;
    cudaGetSymbolAddress((void**)&qlin, g_qlin);
    cudaGetSymbolAddress((void**)&klin, g_klin);
    cudaGetSymbolAddress((void**)&vlin, g_vlin);
    cudaGetSymbolAddress((void**)&o, g_o);

    dim3 t256(256);
    gemm_tf32<<<dim3(DMODEL / GBN, QLEN / GBM, 1), t256>>>(
        hidden, Wq, qlin, Wq, qlin, DMODEL, DMODEL);
    gemm_tf32<<<dim3((NKV * HD) / GBN, QLEN / GBM, 2), t256>>>(
        hidden, Wk, klin, Wv, vlin, NKV * HD, DMODEL);
    rope_kernel<<<dim3(QLEN, NH + 2 * NKV), 128>>>();
    gqk_kernel<<<dim3(QLEN, NH / 8), t256>>>(sorted_channel);
    attn_kernel<<<dim3(QLEN, NH), t256>>>();
    gemm_tf32<<<dim3(DMODEL / GBN, QLEN / GBM, 1), t256>>>(
        o, Wo, out, Wo, out, DMODEL, DMODEL);
}